// round 12
// baseline (speedup 1.0000x reference)
#include <cuda_runtime.h>
#include <math.h>

// Problem dims (fixed by the reference)
#define B_  1024
#define D_  512
#define H_  2048
#define NSTEPS 16

// -------- device scratch (allocation-free: static __device__ globals) --------
__device__ float g_y   [B_ * D_];      // current state y (exact fp32)
__device__ float g_yr  [B_ * D_];      // RNA-tf32-rounded copy of y (MMA input)
__device__ float g_ytmp[B_ * D_];      // RNA-rounded y + c*k (MMA input)
__device__ float g_acc [B_ * D_];      // RK4 accumulator (exact fp32)
__device__ float g_h   [B_ * H_];      // RNA-rounded tanh activations
__device__ float g_W1r [D_ * H_];      // RNA-rounded W1
__device__ float g_W2r [H_ * D_];      // RNA-rounded W2
__device__ float g_part[8][B_ * D_];   // split-K partials for GEMM2 (x8)

// ---------------------------------------------------------------------------
__device__ __forceinline__ float rna_tf32(float x) {
    unsigned r;
    asm("cvt.rna.tf32.f32 %0, %1;" : "=r"(r) : "f"(x));
    return __uint_as_float(r);
}
__device__ __forceinline__ float fast_tanh(float x) {
    float y;
    asm("tanh.approx.f32 %0, %1;" : "=f"(y) : "f"(x));
    return y;
}
// mma.sync m16n8k8 tf32: D = A@B + C, fp32 accumulate. Inputs already tf32-exact.
__device__ __forceinline__ void mma_tf32(float* c, const unsigned* a, const unsigned* b) {
    asm volatile(
        "mma.sync.aligned.m16n8k8.row.col.f32.tf32.tf32.f32 "
        "{%0,%1,%2,%3}, {%4,%5,%6,%7}, {%8,%9}, {%0,%1,%2,%3};"
        : "+f"(c[0]), "+f"(c[1]), "+f"(c[2]), "+f"(c[3])
        : "r"(a[0]), "r"(a[1]), "r"(a[2]), "r"(a[3]),
          "r"(b[0]), "r"(b[1]));
}
__device__ __forceinline__ void cp_async16(float* smem_dst, const float* gmem_src) {
    unsigned s = (unsigned)__cvta_generic_to_shared(smem_dst);
    asm volatile("cp.async.ca.shared.global [%0], [%1], 16;\n" :: "r"(s), "l"(gmem_src));
}
__device__ __forceinline__ void cp_commit() {
    asm volatile("cp.async.commit_group;\n");
}
template <int N>
__device__ __forceinline__ void cp_wait() {
    asm volatile("cp.async.wait_group %0;\n" :: "n"(N));
}

// ---------------------------------------------------------------------------
__global__ void init_y_kernel(const float* __restrict__ x) {
    int i = blockIdx.x * blockDim.x + threadIdx.x;
    if (i < B_ * D_) {
        float v = x[i];
        g_y[i]  = v;
        g_yr[i] = rna_tf32(v);
    }
}
__global__ void prep_weights_kernel(const float* __restrict__ W1,
                                    const float* __restrict__ W2) {
    int i = blockIdx.x * blockDim.x + threadIdx.x;
    if (i < D_ * H_) {
        g_W1r[i] = rna_tf32(W1[i]);
        g_W2r[i] = rna_tf32(W2[i]);
    }
}

// ---------------------------------------------------------------------------
// GEMM1 (R8 config, best measured ~13.5us):
//   g_h[1024,2048] = rna( tanh( Ain[1024,512] @ W1r + b1 + t ) )
//   CTA 64x128, BK=16, 256 threads = 8 warps (2M x 4N), warp tile 32x32.
//   3-stage single-sync cp.async, static smem. Grid (16,16)=256 -> ~14 warps/SM.
__global__ __launch_bounds__(256) void gemm1_tanh(
    const float* __restrict__ b1, float t, int in_sel)
{
    __shared__ float As[3][64 * 20];
    __shared__ float Bs[3][16 * 136];

    const float* __restrict__ Ain = in_sel ? g_ytmp : g_yr;
    const float* __restrict__ W1  = g_W1r;

    const int tid  = threadIdx.x;
    const int lane = tid & 31;
    const int warp = tid >> 5;
    const int g    = lane >> 2;
    const int t4   = lane & 3;
    const int wm   = warp & 1;      // m offset wm*32
    const int wn   = warp >> 1;     // n offset wn*32

    const int bn0 = blockIdx.x * 128;
    const int bm0 = blockIdx.y * 64;

    const int ar = tid >> 2, ac = (tid & 3) * 4;
    auto load_slab = [&](int k0, int s) {
        cp_async16(&As[s][ar * 20 + ac], &Ain[(size_t)(bm0 + ar) * D_ + k0 + ac]);
#pragma unroll
        for (int i = 0; i < 2; i++) {
            int id = tid + 256 * i;
            int r = id >> 5, c = (id & 31) * 4;
            cp_async16(&Bs[s][r * 136 + c], &W1[(size_t)(k0 + r) * H_ + bn0 + c]);
        }
        cp_commit();
    };

    float c[2][4][4];
#pragma unroll
    for (int i = 0; i < 2; i++)
#pragma unroll
        for (int j = 0; j < 4; j++)
#pragma unroll
            for (int e = 0; e < 4; e++) c[i][j][e] = 0.f;

    const int NS = D_ / 16;   // 32 slabs
    load_slab(0, 0);
    load_slab(16, 1);

    for (int si = 0; si < NS; si++) {
        if (si + 1 < NS) cp_wait<1>(); else cp_wait<0>();
        __syncthreads();
        if (si + 2 < NS) load_slab((si + 2) * 16, (si + 2) % 3);

        const unsigned* Asu = reinterpret_cast<const unsigned*>(As[si % 3]);
        const unsigned* Bsu = reinterpret_cast<const unsigned*>(Bs[si % 3]);
#pragma unroll
        for (int kk = 0; kk < 16; kk += 8) {
            unsigned a[2][4], b[4][2];
#pragma unroll
            for (int mt = 0; mt < 2; mt++) {
                int m0 = wm * 32 + mt * 16 + g;
                a[mt][0] = Asu[(m0)     * 20 + kk + t4];
                a[mt][1] = Asu[(m0 + 8) * 20 + kk + t4];
                a[mt][2] = Asu[(m0)     * 20 + kk + t4 + 4];
                a[mt][3] = Asu[(m0 + 8) * 20 + kk + t4 + 4];
            }
#pragma unroll
            for (int nt = 0; nt < 4; nt++) {
                int n0 = wn * 32 + nt * 8 + g;
                b[nt][0] = Bsu[(kk + t4)     * 136 + n0];
                b[nt][1] = Bsu[(kk + t4 + 4) * 136 + n0];
            }
#pragma unroll
            for (int mt = 0; mt < 2; mt++)
#pragma unroll
                for (int nt = 0; nt < 4; nt++)
                    mma_tf32(c[mt][nt], a[mt], b[nt]);
        }
    }

    // epilogue: rna(tanh(c + b1[n] + t)) -> g_h
#pragma unroll
    for (int mt = 0; mt < 2; mt++) {
        int row0 = bm0 + wm * 32 + mt * 16 + g;
#pragma unroll
        for (int nt = 0; nt < 4; nt++) {
            int col = bn0 + wn * 32 + nt * 8 + 2 * t4;
            float bb0 = b1[col] + t, bb1 = b1[col + 1] + t;
            float2 v0, v1;
            v0.x = rna_tf32(fast_tanh(c[mt][nt][0] + bb0));
            v0.y = rna_tf32(fast_tanh(c[mt][nt][1] + bb1));
            v1.x = rna_tf32(fast_tanh(c[mt][nt][2] + bb0));
            v1.y = rna_tf32(fast_tanh(c[mt][nt][3] + bb1));
            *reinterpret_cast<float2*>(&g_h[(size_t)row0 * H_ + col])       = v0;
            *reinterpret_cast<float2*>(&g_h[(size_t)(row0 + 8) * H_ + col]) = v1;
        }
    }
}

// ---------------------------------------------------------------------------
// SMEM layout for GEMM2 (floats), dynamic 56,832 B per CTA:
//   A(s) at s*2560   (128 rows x stride 20)  s = 0..2
//   B(s) at 7680 + s*2176 (16 rows x stride 136)
#define ASLAB 2560
#define BOFF  7680
#define BSLAB 2176

// GEMM2 split-K x8 (R11 geometry, doubled CTA count):
//   partial[z][1024,512] = g_h[:, z*256:(z+1)*256] @ W2r[z*256:(z+1)*256, :]
//   CTA 128x128, K-slice 256, BK=16, 256 threads = 8 warps (2M x 4N),
//   warp tile 64x32 (LDS/MMA = 1.5). Grid (4,8,8) = 256 CTAs -> ~14 warps/SM.
__global__ __launch_bounds__(256) void gemm2_splitk()
{
    extern __shared__ float S[];

    const float* __restrict__ W2 = g_W2r;

    const int tid  = threadIdx.x;
    const int lane = tid & 31;
    const int warp = tid >> 5;
    const int g    = lane >> 2;
    const int t4   = lane & 3;
    const int wm   = warp & 1;      // m offset wm*64
    const int wn   = warp >> 1;     // n offset wn*32

    const int bn0 = blockIdx.x * 128;
    const int bm0 = blockIdx.y * 128;
    const int kb  = blockIdx.z * (H_ / 8);   // K-slice base (256 wide)

    auto load_slab = [&](int k0, int s) {
#pragma unroll
        for (int i = 0; i < 2; i++) {
            int id = tid + 256 * i;
            int r = id >> 2, c = (id & 3) * 4;
            cp_async16(&S[s * ASLAB + r * 20 + c],
                       &g_h[(size_t)(bm0 + r) * H_ + kb + k0 + c]);
        }
#pragma unroll
        for (int i = 0; i < 2; i++) {
            int id = tid + 256 * i;
            int r = id >> 5, c = (id & 31) * 4;
            cp_async16(&S[BOFF + s * BSLAB + r * 136 + c],
                       &W2[(size_t)(kb + k0 + r) * D_ + bn0 + c]);
        }
        cp_commit();
    };

    float c[4][4][4];
#pragma unroll
    for (int i = 0; i < 4; i++)
#pragma unroll
        for (int j = 0; j < 4; j++)
#pragma unroll
            for (int e = 0; e < 4; e++) c[i][j][e] = 0.f;

    const int NS = (H_ / 8) / 16;   // 16 slabs
    load_slab(0, 0);
    load_slab(16, 1);

    for (int si = 0; si < NS; si++) {
        if (si + 1 < NS) cp_wait<1>(); else cp_wait<0>();
        __syncthreads();
        if (si + 2 < NS) load_slab((si + 2) * 16, (si + 2) % 3);

        const unsigned* Asu = reinterpret_cast<const unsigned*>(&S[(si % 3) * ASLAB]);
        const unsigned* Bsu = reinterpret_cast<const unsigned*>(&S[BOFF + (si % 3) * BSLAB]);
#pragma unroll
        for (int kk = 0; kk < 16; kk += 8) {
            unsigned a[4][4], b[4][2];
#pragma unroll
            for (int mt = 0; mt < 4; mt++) {
                int m0 = wm * 64 + mt * 16 + g;
                a[mt][0] = Asu[(m0)     * 20 + kk + t4];
                a[mt][1] = Asu[(m0 + 8) * 20 + kk + t4];
                a[mt][2] = Asu[(m0)     * 20 + kk + t4 + 4];
                a[mt][3] = Asu[(m0 + 8) * 20 + kk + t4 + 4];
            }
#pragma unroll
            for (int nt = 0; nt < 4; nt++) {
                int n0 = wn * 32 + nt * 8 + g;
                b[nt][0] = Bsu[(kk + t4)     * 136 + n0];
                b[nt][1] = Bsu[(kk + t4 + 4) * 136 + n0];
            }
#pragma unroll
            for (int mt = 0; mt < 4; mt++)
#pragma unroll
                for (int nt = 0; nt < 4; nt++)
                    mma_tf32(c[mt][nt], a[mt], b[nt]);
        }
    }

    // write raw partial tile
    float* __restrict__ P = g_part[blockIdx.z];
#pragma unroll
    for (int mt = 0; mt < 4; mt++) {
        int row0 = bm0 + wm * 64 + mt * 16 + g;
#pragma unroll
        for (int nt = 0; nt < 4; nt++) {
            int col = bn0 + wn * 32 + nt * 8 + 2 * t4;
            *reinterpret_cast<float2*>(&P[(size_t)row0 * D_ + col]) =
                make_float2(c[mt][nt][0], c[mt][nt][1]);
            *reinterpret_cast<float2*>(&P[(size_t)(row0 + 8) * D_ + col]) =
                make_float2(c[mt][nt][2], c[mt][nt][3]);
        }
    }
}

// ---------------------------------------------------------------------------
// RK4 epilogue: kv = sum of 8 partials + b2; apply stage update.
// mode: 0 k1 / 1 k2 / 2 k3 / 3 k4 / 4 k4-final(write d_out)
__global__ __launch_bounds__(256) void rk4_epi(
    const float* __restrict__ b2, float dt, int mode, float* __restrict__ yout)
{
    const int i4 = blockIdx.x * blockDim.x + threadIdx.x;   // 0..131071
    const int i  = i4 * 4;
    const int col = i & (D_ - 1);

    float kv[4] = {0.f, 0.f, 0.f, 0.f};
#pragma unroll
    for (int z = 0; z < 8; z++) {
        float4 p = *reinterpret_cast<const float4*>(&g_part[z][i]);
        kv[0] += p.x; kv[1] += p.y; kv[2] += p.z; kv[3] += p.w;
    }
    float4 bb = *reinterpret_cast<const float4*>(&b2[col]);
    kv[0] += bb.x; kv[1] += bb.y; kv[2] += bb.z; kv[3] += bb.w;

    const float half_dt  = 0.5f * dt;
    const float sixth_dt = dt * (1.0f / 6.0f);

    float4 y = *reinterpret_cast<const float4*>(&g_y[i]);
    float yv[4] = {y.x, y.y, y.z, y.w};

    if (mode == 0) {
        float4 ac, yt;
        ac.x = kv[0]; ac.y = kv[1]; ac.z = kv[2]; ac.w = kv[3];
        yt.x = rna_tf32(yv[0] + half_dt * kv[0]);
        yt.y = rna_tf32(yv[1] + half_dt * kv[1]);
        yt.z = rna_tf32(yv[2] + half_dt * kv[2]);
        yt.w = rna_tf32(yv[3] + half_dt * kv[3]);
        *reinterpret_cast<float4*>(&g_acc[i])  = ac;
        *reinterpret_cast<float4*>(&g_ytmp[i]) = yt;
    } else if (mode == 1 || mode == 2) {
        float4 ac = *reinterpret_cast<const float4*>(&g_acc[i]);
        ac.x += 2.f * kv[0]; ac.y += 2.f * kv[1];
        ac.z += 2.f * kv[2]; ac.w += 2.f * kv[3];
        float step = (mode == 1) ? half_dt : dt;
        float4 yt;
        yt.x = rna_tf32(yv[0] + step * kv[0]);
        yt.y = rna_tf32(yv[1] + step * kv[1]);
        yt.z = rna_tf32(yv[2] + step * kv[2]);
        yt.w = rna_tf32(yv[3] + step * kv[3]);
        *reinterpret_cast<float4*>(&g_acc[i])  = ac;
        *reinterpret_cast<float4*>(&g_ytmp[i]) = yt;
    } else if (mode == 3) {
        float4 ac = *reinterpret_cast<const float4*>(&g_acc[i]);
        float4 yn, yr;
        yn.x = yv[0] + sixth_dt * (ac.x + kv[0]);
        yn.y = yv[1] + sixth_dt * (ac.y + kv[1]);
        yn.z = yv[2] + sixth_dt * (ac.z + kv[2]);
        yn.w = yv[3] + sixth_dt * (ac.w + kv[3]);
        yr.x = rna_tf32(yn.x); yr.y = rna_tf32(yn.y);
        yr.z = rna_tf32(yn.z); yr.w = rna_tf32(yn.w);
        *reinterpret_cast<float4*>(&g_y[i])  = yn;
        *reinterpret_cast<float4*>(&g_yr[i]) = yr;
    } else {
        float4 ac = *reinterpret_cast<const float4*>(&g_acc[i]);
        float4 o;
        o.x = yv[0] + sixth_dt * (ac.x + kv[0]);
        o.y = yv[1] + sixth_dt * (ac.y + kv[1]);
        o.z = yv[2] + sixth_dt * (ac.z + kv[2]);
        o.w = yv[3] + sixth_dt * (ac.w + kv[3]);
        *reinterpret_cast<float4*>(&yout[i]) = o;
    }
}

// ---------------------------------------------------------------------------
extern "C" void kernel_launch(void* const* d_in, const int* in_sizes, int n_in,
                              void* d_out, int out_size)
{
    const float* x  = (const float*)d_in[0];   // [1024, 512]
    const float* W1 = (const float*)d_in[1];   // [512, 2048]
    const float* b1 = (const float*)d_in[2];   // [2048]
    const float* W2 = (const float*)d_in[3];   // [2048, 512]
    const float* b2 = (const float*)d_in[4];   // [512]
    float* out = (float*)d_out;                // [1024, 512]

    const float dt = 1.0f / (float)NSTEPS;

    const int SMEM_G2 = (3 * ASLAB + 3 * BSLAB) * 4;   // 56,832 B
    cudaFuncSetAttribute(gemm2_splitk, cudaFuncAttributeMaxDynamicSharedMemorySize, SMEM_G2);

    init_y_kernel<<<(B_ * D_ + 255) / 256, 256>>>(x);
    prep_weights_kernel<<<(D_ * H_ + 255) / 256, 256>>>(W1, W2);

    dim3 grid1(H_ / 128, B_ / 64);         // (16,16)  = 256 CTAs
    dim3 grid2(D_ / 128, B_ / 128, 8);     // (4,8,8)  = 256 CTAs
    dim3 gridE((B_ * D_ / 4) / 256);       // 512 blocks

    for (int s = 0; s < NSTEPS; s++) {
        float t = dt * (float)s;

        gemm1_tanh  <<<grid1, 256>>>(b1, t, /*in_sel=*/0);
        gemm2_splitk<<<grid2, 256, SMEM_G2>>>();
        rk4_epi     <<<gridE, 256>>>(b2, dt, /*mode=*/0, out);

        gemm1_tanh  <<<grid1, 256>>>(b1, t + 0.5f * dt, /*in_sel=*/1);
        gemm2_splitk<<<grid2, 256, SMEM_G2>>>();
        rk4_epi     <<<gridE, 256>>>(b2, dt, /*mode=*/1, out);

        gemm1_tanh  <<<grid1, 256>>>(b1, t + 0.5f * dt, /*in_sel=*/1);
        gemm2_splitk<<<grid2, 256, SMEM_G2>>>();
        rk4_epi     <<<gridE, 256>>>(b2, dt, /*mode=*/2, out);

        gemm1_tanh  <<<grid1, 256>>>(b1, t + dt, /*in_sel=*/1);
        gemm2_splitk<<<grid2, 256, SMEM_G2>>>();
        int mode = (s == NSTEPS - 1) ? 4 : 3;
        rk4_epi     <<<gridE, 256>>>(b2, dt, mode, out);
    }
}